// round 16
// baseline (speedup 1.0000x reference)
#include <cuda_runtime.h>
#include <math.h>
#include <stdint.h>

#define SEQ   1024
#define BSZ   8
#define EMB   512
#define NHEAD 8
#define HDIM  64
#define NROWS (SEQ*BSZ)      // 8192
#define NBH   (BSZ*NHEAD)    // 64
#define FLTMAX 3.402823466e38f
#define T1C 0.6f
#define T2C 0.4f

typedef unsigned long long ull;

// ---------------- packed f32x2 helpers ------------------------------------------
__device__ __forceinline__ ull pack2(float x, float y) {
    ull r; asm("mov.b64 %0, {%1, %2};" : "=l"(r) : "f"(x), "f"(y)); return r;
}
__device__ __forceinline__ ull dup2(float x) { return pack2(x, x); }
__device__ __forceinline__ void fma2(ull& d, ull a, ull b) {
    asm("fma.rn.f32x2 %0, %1, %2, %0;" : "+l"(d) : "l"(a), "l"(b));
}
__device__ __forceinline__ void unpack2(ull v, float& lo, float& hi) {
    asm("mov.b64 {%0, %1}, %2;" : "=f"(lo), "=f"(hi) : "l"(v));
}
// ---------------- cp.async helpers ----------------------------------------------
__device__ __forceinline__ uint32_t sptr(const void* p) {
    return (uint32_t)__cvta_generic_to_shared(p);
}
__device__ __forceinline__ void cpa16(uint32_t s, const void* g) {
    asm volatile("cp.async.cg.shared.global [%0], [%1], 16;" :: "r"(s), "l"(g));
}
__device__ __forceinline__ void cpa_commit() { asm volatile("cp.async.commit_group;"); }
__device__ __forceinline__ void cpa_wait0()  { asm volatile("cp.async.wait_group 0;" ::: "memory"); }
__device__ __forceinline__ void cpa_wait1()  { asm volatile("cp.async.wait_group 1;" ::: "memory"); }

// ---------------- scratch (device globals; no allocation allowed) ---------------
__device__ float g_qs [NROWS*EMB];
__device__ float g_ks [NROWS*EMB];
__device__ float g_qc [NROWS*EMB];
__device__ float g_kc [NROWS*EMB];
__device__ float g_v  [NROWS*EMB];
__device__ float g_qsT[NBH*HDIM*SEQ];   // [bh][d][t], q pre-scaled by 1/8
__device__ float g_ksT[NBH*HDIM*SEQ];
__device__ float g_qcT[NBH*HDIM*SEQ];
__device__ float g_kcT[NBH*HDIM*SEQ];
__device__ float g_o  [NROWS*EMB];
__device__ int   g_idx[NBH*SEQ];

struct GemmBatch {
    const float* x[5];
    float*       c[5];
    int          woff[5];
};
struct TransBatch {
    const float* src[4];
    float*       dst[4];
    float        scale[4];
};

// -------- fp32 GEMM (FFMA2, k-pair form): 128M x 64N tile, 256 thr --------------
// X,W staged in NATURAL row-major smem via cp.async (no transpose, no STS).
// acc(m,n) packs (even-k, odd-k) partial sums -> zero dup movs in inner loop.
// Per thread: 8m x 4n.  Double-buffered.
#define GPAD 20

__device__ __forceinline__ void gemm_issue(int buf, int k0,
                                           float (*Xs)[128][GPAD], float (*Ws)[64][GPAD],
                                           const float* X, const float* W,
                                           int bm, int bn, int tid) {
    {
        int row = tid >> 2, kc = (tid & 3) << 2;
        cpa16(sptr(&Xs[buf][row][kc]), X + (size_t)(bm + row) * EMB + k0 + kc);
        int row2 = (tid + 256) >> 2, kc2 = ((tid + 256) & 3) << 2;
        cpa16(sptr(&Xs[buf][row2][kc2]), X + (size_t)(bm + row2) * EMB + k0 + kc2);
    }
    {
        int row = tid >> 2, kc = (tid & 3) << 2;
        if (row < 64)
            cpa16(sptr(&Ws[buf][row][kc]), W + (size_t)(bn + row) * EMB + k0 + kc);
        int row2 = (tid + 256) >> 2, kc2 = ((tid + 256) & 3) << 2;
        if (row2 < 64)
            cpa16(sptr(&Ws[buf][row2][kc2]), W + (size_t)(bn + row2) * EMB + k0 + kc2);
    }
    cpa_commit();
}

__device__ __forceinline__ void gemm_body(const float* __restrict__ X,
                                          const float* __restrict__ W,
                                          const float* __restrict__ bias,
                                          float* __restrict__ C, float bscale) {
    __shared__ float Xs[2][128][GPAD];
    __shared__ float Ws[2][64][GPAD];
    const int bm = blockIdx.y << 7;
    const int bn = blockIdx.x << 6;
    const int tid = threadIdx.x;
    const int mg = tid >> 4;        // 16 groups x 8 m
    const int ng = tid & 15;        // 16 groups x 4 n

    ull acc[8][4];
#pragma unroll
    for (int i = 0; i < 8; i++)
#pragma unroll
        for (int j = 0; j < 4; j++) acc[i][j] = 0ull;

    gemm_issue(0, 0, Xs, Ws, X, W, bm, bn, tid);

    for (int it = 0; it < 32; it++) {
        const int buf = it & 1;
        if (it + 1 < 32) {
            gemm_issue(buf ^ 1, (it + 1) << 4, Xs, Ws, X, W, bm, bn, tid);
            cpa_wait1();
        } else {
            cpa_wait0();
        }
        __syncthreads();

#pragma unroll
        for (int kk = 0; kk < 16; kk += 4) {
            ull b01[4], b23[4];
#pragma unroll
            for (int j = 0; j < 4; j++) {
                ulonglong2 bv = *(const ulonglong2*)&Ws[buf][(ng << 2) + j][kk];
                b01[j] = bv.x; b23[j] = bv.y;
            }
#pragma unroll
            for (int i = 0; i < 8; i++) {
                ulonglong2 av = *(const ulonglong2*)&Xs[buf][(mg << 3) + i][kk];
#pragma unroll
                for (int j = 0; j < 4; j++) {
                    fma2(acc[i][j], av.x, b01[j]);
                    fma2(acc[i][j], av.y, b23[j]);
                }
            }
        }
        __syncthreads();   // all reads of buf done before it is refilled
    }

    float bb[4];
#pragma unroll
    for (int j = 0; j < 4; j++) bb[j] = bias[bn + (ng << 2) + j] * bscale;
#pragma unroll
    for (int i = 0; i < 8; i++) {
        float4 o;
        float lo, hi;
        unpack2(acc[i][0], lo, hi); o.x = lo + hi + bb[0];
        unpack2(acc[i][1], lo, hi); o.y = lo + hi + bb[1];
        unpack2(acc[i][2], lo, hi); o.z = lo + hi + bb[2];
        unpack2(acc[i][3], lo, hi); o.w = lo + hi + bb[3];
        *(float4*)&C[(size_t)(bm + (mg << 3) + i) * EMB + bn + (ng << 2)] = o;
    }
}

__global__ __launch_bounds__(256, 2)
void gemm_bias5(GemmBatch gb, const float* __restrict__ W, const float* __restrict__ bias) {
    const int z = blockIdx.z;
    gemm_body(gb.x[z], W + (size_t)gb.woff[z] * EMB, bias + gb.woff[z], gb.c[z], 1.0f);
}

__global__ __launch_bounds__(256, 2)
void gemm_bias(const float* __restrict__ X, const float* __restrict__ W,
               const float* __restrict__ bias, float* __restrict__ C, float bscale) {
    gemm_body(X, W, bias, C, bscale);
}

// ------- head transpose x4 ------------------------------------------------------
__global__ __launch_bounds__(256)
void transpose_head4(TransBatch tb) {
    __shared__ float tile[32][33];
    const int z = blockIdx.z;
    const int var = z >> 6, bh = z & 63;
    const int b = bh >> 3, h = bh & 7;
    const float* in  = tb.src[var];
    float* out = tb.dst[var];
    const float scale = tb.scale[var];
    const int t0 = blockIdx.x << 5;
    const int d0 = blockIdx.y << 5;
    const int tx = threadIdx.x & 31, ty = threadIdx.x >> 5;
#pragma unroll
    for (int i = 0; i < 32; i += 8)
        tile[ty + i][tx] = in[(size_t)(t0 + ty + i) * (BSZ*EMB) + b * EMB + h * HDIM + d0 + tx] * scale;
    __syncthreads();
#pragma unroll
    for (int i = 0; i < 32; i += 8)
        out[(size_t)(bh * HDIM + d0 + ty + i) * SEQ + t0 + tx] = tile[tx][ty + i];
}

// ---------------- SSA kernel: scores + running argmax ---------------------------
// 128q x 64s tiles. smem: qT[64][128], kT[2][64][64]. cp.async double-buffered k.
#define SSA_SM_FLOATS (64*128 + 2*64*64)

__device__ __forceinline__ void ssa_issue(int s0, float* kbuf, int tid, int bh) {
    for (int i = tid; i < 1024; i += 256) {
        int d = i >> 4, g = (i & 15) << 2;
        cpa16(sptr(kbuf + d*64 + g), &g_kcT[(size_t)(bh*HDIM + d)*SEQ + s0 + g]);
    }
    cpa_commit();
}

__global__ __launch_bounds__(256, 2)
void ssa_kernel(const float* __restrict__ sem_map) {
    extern __shared__ float sm[];
    float* qTs = sm;            // [d][128]
    float* kT  = sm + 64*128;   // 2 buffers of [d][64]

    const int bh = blockIdx.y;
    const int q0 = blockIdx.x << 7;
    const int tid = threadIdx.x;
    const int rg = tid >> 4;    // 16 x 8q
    const int cg = tid & 15;    // 16 x 4s

    for (int i = tid; i < 2048; i += 256) {
        int d = i >> 5, g = (i & 31) << 2;
        *(float4*)&qTs[d*128 + g] = *(const float4*)&g_qcT[(size_t)(bh*HDIM + d)*SEQ + q0 + g];
    }

    float bsc[8];
    int   bix[8];
#pragma unroll
    for (int i = 0; i < 8; i++) { bsc[i] = -FLTMAX; bix[i] = 0; }

    const float* qb = &qTs[rg << 3];
    ssa_issue(0, kT, tid, bh);

    for (int it = 0; it < 16; it++) {
        const int s0 = it << 6;
        cpa_wait0();
        __syncthreads();
        if (it + 1 < 16) ssa_issue(s0 + 64, kT + ((it + 1) & 1) * 4096, tid, bh);

        const float* kb = kT + (it & 1) * 4096 + (cg << 2);

        ull sc2[4][4];
#pragma unroll
        for (int i = 0; i < 4; i++)
#pragma unroll
            for (int j = 0; j < 4; j++) sc2[i][j] = 0ull;

#pragma unroll 4
        for (int d = 0; d < 64; d++) {
            ulonglong2 q01 = *(const ulonglong2*)(qb + d*128);
            ulonglong2 q23 = *(const ulonglong2*)(qb + d*128 + 4);
            float4 kv = *(const float4*)(kb + d*64);
            ull k0 = dup2(kv.x), k1 = dup2(kv.y), k2 = dup2(kv.z), k3 = dup2(kv.w);
            fma2(sc2[0][0], q01.x, k0); fma2(sc2[0][1], q01.x, k1);
            fma2(sc2[0][2], q01.x, k2); fma2(sc2[0][3], q01.x, k3);
            fma2(sc2[1][0], q01.y, k0); fma2(sc2[1][1], q01.y, k1);
            fma2(sc2[1][2], q01.y, k2); fma2(sc2[1][3], q01.y, k3);
            fma2(sc2[2][0], q23.x, k0); fma2(sc2[2][1], q23.x, k1);
            fma2(sc2[2][2], q23.x, k2); fma2(sc2[2][3], q23.x, k3);
            fma2(sc2[3][0], q23.y, k0); fma2(sc2[3][1], q23.y, k1);
            fma2(sc2[3][2], q23.y, k2); fma2(sc2[3][3], q23.y, k3);
        }

#pragma unroll
        for (int qp = 0; qp < 4; qp++) {
            float s0v[4], s1v[4];
#pragma unroll
            for (int j = 0; j < 4; j++) unpack2(sc2[qp][j], s0v[j], s1v[j]);
            int i0 = (qp << 1), i1 = i0 + 1;
            float4 mk0 = *(const float4*)&sem_map[(size_t)(q0 + (rg<<3) + i0)*SEQ + s0 + (cg<<2)];
            float4 mk1 = *(const float4*)&sem_map[(size_t)(q0 + (rg<<3) + i1)*SEQ + s0 + (cg<<2)];
            float ma[4] = {mk0.x, mk0.y, mk0.z, mk0.w};
            float mb[4] = {mk1.x, mk1.y, mk1.z, mk1.w};
#pragma unroll
            for (int j = 0; j < 4; j++) {
                float va = (ma[j] < 0.5f) ? -FLTMAX : s0v[j];
                float vb = (mb[j] < 0.5f) ? -FLTMAX : s1v[j];
                if (va > bsc[i0]) { bsc[i0] = va; bix[i0] = s0 + (cg<<2) + j; }
                if (vb > bsc[i1]) { bsc[i1] = vb; bix[i1] = s0 + (cg<<2) + j; }
            }
        }
    }

#pragma unroll
    for (int i = 0; i < 8; i++) {
        float bs = bsc[i]; int bi = bix[i];
#pragma unroll
        for (int off = 1; off < 16; off <<= 1) {
            float os = __shfl_xor_sync(0xffffffffu, bs, off, 16);
            int   oi = __shfl_xor_sync(0xffffffffu, bi, off, 16);
            if (os > bs || (os == bs && oi < bi)) { bs = os; bi = oi; }
        }
        if (cg == 0) g_idx[bh*SEQ + q0 + (rg<<3) + i] = bi;
    }
}

// ---------------- SCA kernel (R13 champion): 64q x 64s, 128 thr, pipelined ------
#define SCA_QT   0
#define SCA_KT   4096
#define SCA_VT   8192
#define SCA_WT   12544
#define SCA_L    16896
#define SCA_SM_FLOATS 16960

__device__ __forceinline__ void sca_issue_k(int s0, float* kT, int tid, int bh) {
    for (int i = tid; i < 1024; i += 128) {
        int d = i >> 4, g = (i & 15) << 2;
        cpa16(sptr(kT + d*64 + g), &g_ksT[(size_t)(bh*HDIM + d)*SEQ + s0 + g]);
    }
    cpa_commit();
}
__device__ __forceinline__ void sca_issue_v(int s0, float* vT, int tid, int b, int h) {
    for (int i = tid; i < 1024; i += 128) {
        int d = i >> 4, g = (i & 15) << 2;
        cpa16(sptr(vT + d*68 + g), &g_v[(size_t)((s0 + d)*BSZ + b)*EMB + h*HDIM + g]);
    }
    cpa_commit();
}

__global__ __launch_bounds__(128)
void sca_kernel(const float* __restrict__ sem_map, float* __restrict__ Ocomb) {
    extern __shared__ float sm[];
    float* qTs  = sm + SCA_QT;
    float* kT   = sm + SCA_KT;
    float* vT   = sm + SCA_VT;
    float* wts  = sm + SCA_WT;
    float* sl   = sm + SCA_L;

    const int bh = blockIdx.y, b = bh >> 3, h = bh & 7;
    const int q0 = blockIdx.x << 6;
    const int tid = threadIdx.x;
    const int rg = tid >> 4;     // 8 groups x 8q
    const int cg = tid & 15;     // 16 groups x 4s

    for (int i = tid; i < 1024; i += 128) {
        int d = i >> 4, g = (i & 15) << 2;
        *(float4*)&qTs[d*64 + g] = *(const float4*)&g_qsT[(size_t)(bh*HDIM + d)*SEQ + q0 + g];
    }

    float lrun[8];
#pragma unroll
    for (int i = 0; i < 8; i++) lrun[i] = 0.f;

    ull acc2[4][4];
#pragma unroll
    for (int i = 0; i < 4; i++)
#pragma unroll
        for (int j = 0; j < 4; j++) acc2[i][j] = 0ull;

    const float* qb = &qTs[rg << 3];
    const float* kb = &kT[cg << 2];
    const float* wb = &wts[rg << 3];
    const float* vb = &vT[cg << 2];

    sca_issue_k(0, kT, tid, bh);          // group: k(0)

    for (int it = 0; it < 16; it++) {
        const int s0 = it << 6;
        __syncthreads();                   // prev PV done reading vT/wt
        sca_issue_v(s0, vT, tid, b, h);    // group: v(it) — loads during score
        cpa_wait1();                       // k(it) retired; v(it) in flight
        __syncthreads();

        ull sc2[4][4];
#pragma unroll
        for (int i = 0; i < 4; i++)
#pragma unroll
            for (int j = 0; j < 4; j++) sc2[i][j] = 0ull;

#pragma unroll 4
        for (int d = 0; d < 64; d++) {
            ulonglong2 q01 = *(const ulonglong2*)(qb + d*64);
            ulonglong2 q23 = *(const ulonglong2*)(qb + d*64 + 4);
            float4 kv = *(const float4*)(kb + d*64);
            ull k0 = dup2(kv.x), k1 = dup2(kv.y), k2 = dup2(kv.z), k3 = dup2(kv.w);
            fma2(sc2[0][0], q01.x, k0); fma2(sc2[0][1], q01.x, k1);
            fma2(sc2[0][2], q01.x, k2); fma2(sc2[0][3], q01.x, k3);
            fma2(sc2[1][0], q01.y, k0); fma2(sc2[1][1], q01.y, k1);
            fma2(sc2[1][2], q01.y, k2); fma2(sc2[1][3], q01.y, k3);
            fma2(sc2[2][0], q23.x, k0); fma2(sc2[2][1], q23.x, k1);
            fma2(sc2[2][2], q23.x, k2); fma2(sc2[2][3], q23.x, k3);
            fma2(sc2[3][0], q23.y, k0); fma2(sc2[3][1], q23.y, k1);
            fma2(sc2[3][2], q23.y, k2); fma2(sc2[3][3], q23.y, k3);
        }

#pragma unroll
        for (int qp = 0; qp < 4; qp++) {
            float sA[4], sB[4];
#pragma unroll
            for (int j = 0; j < 4; j++) unpack2(sc2[qp][j], sA[j], sB[j]);
            int iA = qp << 1, iB = iA + 1;
            float4 mkA = *(const float4*)&sem_map[(size_t)(q0 + (rg<<3) + iA)*SEQ + s0 + (cg<<2)];
            float4 mkB = *(const float4*)&sem_map[(size_t)(q0 + (rg<<3) + iB)*SEQ + s0 + (cg<<2)];
            float wA[4], wB[4];
            wA[0] = (mkA.x < 0.5f) ? 0.f : __expf(sA[0]);
            wA[1] = (mkA.y < 0.5f) ? 0.f : __expf(sA[1]);
            wA[2] = (mkA.z < 0.5f) ? 0.f : __expf(sA[2]);
            wA[3] = (mkA.w < 0.5f) ? 0.f : __expf(sA[3]);
            wB[0] = (mkB.x < 0.5f) ? 0.f : __expf(sB[0]);
            wB[1] = (mkB.y < 0.5f) ? 0.f : __expf(sB[1]);
            wB[2] = (mkB.z < 0.5f) ? 0.f : __expf(sB[2]);
            wB[3] = (mkB.w < 0.5f) ? 0.f : __expf(sB[3]);
            lrun[iA] += (wA[0] + wA[1]) + (wA[2] + wA[3]);
            lrun[iB] += (wB[0] + wB[1]) + (wB[2] + wB[3]);
#pragma unroll
            for (int j = 0; j < 4; j++)
                *(ull*)&wts[((cg<<2)+j)*68 + (rg<<3) + (qp<<1)] = pack2(wA[j], wB[j]);
        }
        __syncthreads();                   // kT free; wt written

        if (it + 1 < 16) {
            sca_issue_k(s0 + 64, kT, tid, bh);  // k(it+1) — loads during PV
            cpa_wait1();                   // v(it) retired; k(it+1) in flight
        } else {
            cpa_wait0();                   // v(15) retired
        }
        __syncthreads();

#pragma unroll 4
        for (int s = 0; s < 64; s++) {
            ulonglong2 w01 = *(const ulonglong2*)(wb + s*68);
            ulonglong2 w23 = *(const ulonglong2*)(wb + s*68 + 4);
            float4 vv = *(const float4*)(vb + s*68);
            ull v0 = dup2(vv.x), v1 = dup2(vv.y), v2 = dup2(vv.z), v3 = dup2(vv.w);
            fma2(acc2[0][0], w01.x, v0); fma2(acc2[0][1], w01.x, v1);
            fma2(acc2[0][2], w01.x, v2); fma2(acc2[0][3], w01.x, v3);
            fma2(acc2[1][0], w01.y, v0); fma2(acc2[1][1], w01.y, v1);
            fma2(acc2[1][2], w01.y, v2); fma2(acc2[1][3], w01.y, v3);
            fma2(acc2[2][0], w23.x, v0); fma2(acc2[2][1], w23.x, v1);
            fma2(acc2[2][2], w23.x, v2); fma2(acc2[2][3], w23.x, v3);
            fma2(acc2[3][0], w23.y, v0); fma2(acc2[3][1], w23.y, v1);
            fma2(acc2[3][2], w23.y, v2); fma2(acc2[3][3], w23.y, v3);
        }
    }

#pragma unroll
    for (int i = 0; i < 8; i++) {
        float s = lrun[i];
#pragma unroll
        for (int off = 1; off < 16; off <<= 1)
            s += __shfl_xor_sync(0xffffffffu, s, off, 16);
        if (cg == 0) sl[(rg<<3) + i] = s;
    }
    __syncthreads();

#pragma unroll
    for (int qp = 0; qp < 4; qp++) {
        float aA[4], aB[4];
#pragma unroll
        for (int j = 0; j < 4; j++) unpack2(acc2[qp][j], aA[j], aB[j]);
        int rA = (rg<<3) + (qp<<1), rB = rA + 1;
        float rlA = 1.0f / sl[rA];
        float rlB = 1.0f / sl[rB];
        int biA = g_idx[bh*SEQ + q0 + rA];
        int biB = g_idx[bh*SEQ + q0 + rB];
        float4 vA = *(const float4*)&g_v[(size_t)(biA*BSZ + b)*EMB + h*HDIM + (cg<<2)];
        float4 vB = *(const float4*)&g_v[(size_t)(biB*BSZ + b)*EMB + h*HDIM + (cg<<2)];
        float4 oA, oB;
        oA.x = T1C*aA[0]*rlA + T2C*vA.x;  oA.y = T1C*aA[1]*rlA + T2C*vA.y;
        oA.z = T1C*aA[2]*rlA + T2C*vA.z;  oA.w = T1C*aA[3]*rlA + T2C*vA.w;
        oB.x = T1C*aB[0]*rlB + T2C*vB.x;  oB.y = T1C*aB[1]*rlB + T2C*vB.y;
        oB.z = T1C*aB[2]*rlB + T2C*vB.z;  oB.w = T1C*aB[3]*rlB + T2C*vB.w;
        *(float4*)&Ocomb[(size_t)((q0 + rA)*BSZ + b)*EMB + h*HDIM + (cg<<2)] = oA;
        *(float4*)&Ocomb[(size_t)((q0 + rB)*BSZ + b)*EMB + h*HDIM + (cg<<2)] = oB;
    }
}

// -------------------------------------------------------------------------------
extern "C" void kernel_launch(void* const* d_in, const int* in_sizes, int n_in,
                              void* d_out, int out_size) {
    const float* query = (const float*)d_in[0];
    const float* key   = (const float*)d_in[1];
    const float* value = (const float*)d_in[2];
    const float* qsem  = (const float*)d_in[3];
    const float* ksem  = (const float*)d_in[4];
    const float* smap  = (const float*)d_in[5];
    const float* Wi    = (const float*)d_in[6];
    const float* bi    = (const float*)d_in[7];
    const float* Wo    = (const float*)d_in[8];
    const float* bo    = (const float*)d_in[9];
    float* out = (float*)d_out;

    float *p_qs, *p_ks, *p_qc, *p_kc, *p_v, *p_qsT, *p_ksT, *p_qcT, *p_kcT, *p_o;
    cudaGetSymbolAddress((void**)&p_qs,  g_qs);
    cudaGetSymbolAddress((void**)&p_ks,  g_ks);
    cudaGetSymbolAddress((void**)&p_qc,  g_qc);
    cudaGetSymbolAddress((void**)&p_kc,  g_kc);
    cudaGetSymbolAddress((void**)&p_v,   g_v);
    cudaGetSymbolAddress((void**)&p_qsT, g_qsT);
    cudaGetSymbolAddress((void**)&p_ksT, g_ksT);
    cudaGetSymbolAddress((void**)&p_qcT, g_qcT);
    cudaGetSymbolAddress((void**)&p_kcT, g_kcT);
    cudaGetSymbolAddress((void**)&p_o,   g_o);

    static int init_done = 0;
    if (!init_done) {
        cudaFuncSetAttribute(sca_kernel, cudaFuncAttributeMaxDynamicSharedMemorySize, SCA_SM_FLOATS*4);
        cudaFuncSetAttribute(ssa_kernel, cudaFuncAttributeMaxDynamicSharedMemorySize, SSA_SM_FLOATS*4);
        init_done = 1;
    }

    GemmBatch gb;
    gb.x[0] = qsem;  gb.c[0] = p_qs; gb.woff[0] = 0;
    gb.x[1] = ksem;  gb.c[1] = p_ks; gb.woff[1] = 512;
    gb.x[2] = query; gb.c[2] = p_qc; gb.woff[2] = 0;
    gb.x[3] = key;   gb.c[3] = p_kc; gb.woff[3] = 512;
    gb.x[4] = value; gb.c[4] = p_v;  gb.woff[4] = 1024;
    gemm_bias5<<<dim3(EMB/64, NROWS/128, 5), 256>>>(gb, Wi, bi);

    TransBatch tb;
    tb.src[0] = p_qs; tb.dst[0] = p_qsT; tb.scale[0] = 0.125f;
    tb.src[1] = p_ks; tb.dst[1] = p_ksT; tb.scale[1] = 1.0f;
    tb.src[2] = p_qc; tb.dst[2] = p_qcT; tb.scale[2] = 0.125f;
    tb.src[3] = p_kc; tb.dst[3] = p_kcT; tb.scale[3] = 1.0f;
    transpose_head4<<<dim3(SEQ/32, HDIM/32, 4*NBH), 256>>>(tb);

    ssa_kernel<<<dim3(SEQ/128, NBH), 256, SSA_SM_FLOATS*4>>>(smap);
    sca_kernel<<<dim3(SEQ/64, NBH), 128, SCA_SM_FLOATS*4>>>(smap, p_o);

    gemm_bias<<<dim3(EMB/64, NROWS/128), 256>>>(p_o, Wo, bo, out, T1C + T2C);
}

// round 17
// speedup vs baseline: 1.3337x; 1.3337x over previous
#include <cuda_runtime.h>
#include <math.h>
#include <stdint.h>

#define SEQ   1024
#define BSZ   8
#define EMB   512
#define NHEAD 8
#define HDIM  64
#define NROWS (SEQ*BSZ)      // 8192
#define NBH   (BSZ*NHEAD)    // 64
#define FLTMAX 3.402823466e38f
#define T1C 0.6f
#define T2C 0.4f

typedef unsigned long long ull;

// ---------------- packed f32x2 helpers ------------------------------------------
__device__ __forceinline__ ull pack2(float x, float y) {
    ull r; asm("mov.b64 %0, {%1, %2};" : "=l"(r) : "f"(x), "f"(y)); return r;
}
__device__ __forceinline__ ull dup2(float x) { return pack2(x, x); }
__device__ __forceinline__ void fma2(ull& d, ull a, ull b) {
    asm("fma.rn.f32x2 %0, %1, %2, %0;" : "+l"(d) : "l"(a), "l"(b));
}
__device__ __forceinline__ void unpack2(ull v, float& lo, float& hi) {
    asm("mov.b64 {%0, %1}, %2;" : "=f"(lo), "=f"(hi) : "l"(v));
}
// ---------------- cp.async helpers ----------------------------------------------
__device__ __forceinline__ uint32_t sptr(const void* p) {
    return (uint32_t)__cvta_generic_to_shared(p);
}
__device__ __forceinline__ void cpa16(uint32_t s, const void* g) {
    asm volatile("cp.async.cg.shared.global [%0], [%1], 16;" :: "r"(s), "l"(g));
}
__device__ __forceinline__ void cpa_commit() { asm volatile("cp.async.commit_group;"); }
__device__ __forceinline__ void cpa_wait0()  { asm volatile("cp.async.wait_group 0;" ::: "memory"); }
__device__ __forceinline__ void cpa_wait1()  { asm volatile("cp.async.wait_group 1;" ::: "memory"); }

// ---------------- scratch (device globals; no allocation allowed) ---------------
__device__ float g_qs [NROWS*EMB];
__device__ float g_ks [NROWS*EMB];
__device__ float g_qc [NROWS*EMB];
__device__ float g_kc [NROWS*EMB];
__device__ float g_v  [NROWS*EMB];
__device__ float g_qsT[NBH*HDIM*SEQ];   // [bh][d][t], q pre-scaled by 1/8
__device__ float g_ksT[NBH*HDIM*SEQ];
__device__ float g_qcT[NBH*HDIM*SEQ];
__device__ float g_kcT[NBH*HDIM*SEQ];
__device__ float g_o  [NROWS*EMB];
__device__ int   g_idx[NBH*SEQ];

struct GemmBatch {
    const float* x[5];
    float*       c[5];
    int          woff[5];
};
struct TransBatch {
    const float* src[4];
    float*       dst[4];
    float        scale[4];
};

// -------- fp32 GEMM (FFMA2): 128x128 tile, 256 thr, 8Mx8N/thread (R13 form) -----
// Double-buffered smem: ONE __syncthreads per 16-k iteration.
__device__ __forceinline__ void gemm_body(const float* __restrict__ X,
                                          const float* __restrict__ W,
                                          const float* __restrict__ bias,
                                          float* __restrict__ C, float bscale) {
    __shared__ float As[2][16][132];
    __shared__ float Bs[2][16][132];
    const int bm = blockIdx.y << 7;
    const int bn = blockIdx.x << 7;
    const int tid = threadIdx.x;
    const int mg = tid >> 4;
    const int ng = tid & 15;
    const int ar = tid >> 1;
    const int af = (tid & 1) << 3;

    ull acc2[4][8];
#pragma unroll
    for (int p = 0; p < 4; p++)
#pragma unroll
        for (int j = 0; j < 8; j++) acc2[p][j] = 0ull;

    const float* xp = X + (size_t)(bm + ar) * EMB + af;
    const float* wp = W + (size_t)(bn + ar) * EMB + af;

    {
        float4 xa0 = *(const float4*)(xp);
        float4 xa1 = *(const float4*)(xp + 4);
        float4 wb0 = *(const float4*)(wp);
        float4 wb1 = *(const float4*)(wp + 4);
        As[0][af+0][ar] = xa0.x; As[0][af+1][ar] = xa0.y; As[0][af+2][ar] = xa0.z; As[0][af+3][ar] = xa0.w;
        As[0][af+4][ar] = xa1.x; As[0][af+5][ar] = xa1.y; As[0][af+6][ar] = xa1.z; As[0][af+7][ar] = xa1.w;
        Bs[0][af+0][ar] = wb0.x; Bs[0][af+1][ar] = wb0.y; Bs[0][af+2][ar] = wb0.z; Bs[0][af+3][ar] = wb0.w;
        Bs[0][af+4][ar] = wb1.x; Bs[0][af+5][ar] = wb1.y; Bs[0][af+6][ar] = wb1.z; Bs[0][af+7][ar] = wb1.w;
    }
    __syncthreads();

    float4 xa0, xa1, wb0, wb1;
    xa0 = *(const float4*)(xp + 16);
    xa1 = *(const float4*)(xp + 20);
    wb0 = *(const float4*)(wp + 16);
    wb1 = *(const float4*)(wp + 20);

    for (int it = 0; it < 32; it++) {
        const int cur = it & 1;
#pragma unroll
        for (int k = 0; k < 16; k++) {
            ulonglong2 a01 = *(const ulonglong2*)&As[cur][k][mg << 3];
            ulonglong2 a23 = *(const ulonglong2*)&As[cur][k][(mg << 3) + 4];
            float4 b0 = *(const float4*)&Bs[cur][k][ng << 3];
            float4 b1 = *(const float4*)&Bs[cur][k][(ng << 3) + 4];
            ull bd[8];
            bd[0] = dup2(b0.x); bd[1] = dup2(b0.y); bd[2] = dup2(b0.z); bd[3] = dup2(b0.w);
            bd[4] = dup2(b1.x); bd[5] = dup2(b1.y); bd[6] = dup2(b1.z); bd[7] = dup2(b1.w);
#pragma unroll
            for (int j = 0; j < 8; j++) {
                fma2(acc2[0][j], a01.x, bd[j]);
                fma2(acc2[1][j], a01.y, bd[j]);
                fma2(acc2[2][j], a23.x, bd[j]);
                fma2(acc2[3][j], a23.y, bd[j]);
            }
        }
        if (it + 1 < 32) {
            const int nxt = cur ^ 1;
            As[nxt][af+0][ar] = xa0.x; As[nxt][af+1][ar] = xa0.y; As[nxt][af+2][ar] = xa0.z; As[nxt][af+3][ar] = xa0.w;
            As[nxt][af+4][ar] = xa1.x; As[nxt][af+5][ar] = xa1.y; As[nxt][af+6][ar] = xa1.z; As[nxt][af+7][ar] = xa1.w;
            Bs[nxt][af+0][ar] = wb0.x; Bs[nxt][af+1][ar] = wb0.y; Bs[nxt][af+2][ar] = wb0.z; Bs[nxt][af+3][ar] = wb0.w;
            Bs[nxt][af+4][ar] = wb1.x; Bs[nxt][af+5][ar] = wb1.y; Bs[nxt][af+6][ar] = wb1.z; Bs[nxt][af+7][ar] = wb1.w;
            if (it + 2 < 32) {
                const int k0 = (it + 2) << 4;
                xa0 = *(const float4*)(xp + k0);
                xa1 = *(const float4*)(xp + k0 + 4);
                wb0 = *(const float4*)(wp + k0);
                wb1 = *(const float4*)(wp + k0 + 4);
            }
        }
        __syncthreads();
    }

    float bb[8];
#pragma unroll
    for (int j = 0; j < 8; j++) bb[j] = bias[bn + (ng<<3) + j] * bscale;
#pragma unroll
    for (int p = 0; p < 4; p++) {
        float lo[8], hi[8];
#pragma unroll
        for (int j = 0; j < 8; j++) unpack2(acc2[p][j], lo[j], hi[j]);
        int r0 = bm + (mg << 3) + (p << 1);
        float* c0 = &C[(size_t)r0 * EMB + bn + (ng<<3)];
        float* c1 = &C[(size_t)(r0+1) * EMB + bn + (ng<<3)];
        *(float4*)(c0)   = make_float4(lo[0]+bb[0], lo[1]+bb[1], lo[2]+bb[2], lo[3]+bb[3]);
        *(float4*)(c0+4) = make_float4(lo[4]+bb[4], lo[5]+bb[5], lo[6]+bb[6], lo[7]+bb[7]);
        *(float4*)(c1)   = make_float4(hi[0]+bb[0], hi[1]+bb[1], hi[2]+bb[2], hi[3]+bb[3]);
        *(float4*)(c1+4) = make_float4(hi[4]+bb[4], hi[5]+bb[5], hi[6]+bb[6], hi[7]+bb[7]);
    }
}

__global__ __launch_bounds__(256, 2)
void gemm_bias5(GemmBatch gb, const float* __restrict__ W, const float* __restrict__ bias) {
    const int z = blockIdx.z;
    gemm_body(gb.x[z], W + (size_t)gb.woff[z] * EMB, bias + gb.woff[z], gb.c[z], 1.0f);
}

__global__ __launch_bounds__(256, 2)
void gemm_bias(const float* __restrict__ X, const float* __restrict__ W,
               const float* __restrict__ bias, float* __restrict__ C, float bscale) {
    gemm_body(X, W, bias, C, bscale);
}

// ------- head transpose x4 ------------------------------------------------------
__global__ __launch_bounds__(256)
void transpose_head4(TransBatch tb) {
    __shared__ float tile[32][33];
    const int z = blockIdx.z;
    const int var = z >> 6, bh = z & 63;
    const int b = bh >> 3, h = bh & 7;
    const float* in  = tb.src[var];
    float* out = tb.dst[var];
    const float scale = tb.scale[var];
    const int t0 = blockIdx.x << 5;
    const int d0 = blockIdx.y << 5;
    const int tx = threadIdx.x & 31, ty = threadIdx.x >> 5;
#pragma unroll
    for (int i = 0; i < 32; i += 8)
        tile[ty + i][tx] = in[(size_t)(t0 + ty + i) * (BSZ*EMB) + b * EMB + h * HDIM + d0 + tx] * scale;
    __syncthreads();
#pragma unroll
    for (int i = 0; i < 32; i += 8)
        out[(size_t)(bh * HDIM + d0 + ty + i) * SEQ + t0 + tx] = tile[tx][ty + i];
}

// ---------------- SSA kernel: scores + running argmax ---------------------------
// 128q x 64s tiles. smem: qT[64][128], kT[2][64][64]. cp.async double-buffered k.
#define SSA_SM_FLOATS (64*128 + 2*64*64)

__device__ __forceinline__ void ssa_issue(int s0, float* kbuf, int tid, int bh) {
    for (int i = tid; i < 1024; i += 256) {
        int d = i >> 4, g = (i & 15) << 2;
        cpa16(sptr(kbuf + d*64 + g), &g_kcT[(size_t)(bh*HDIM + d)*SEQ + s0 + g]);
    }
    cpa_commit();
}

__global__ __launch_bounds__(256, 2)
void ssa_kernel(const float* __restrict__ sem_map) {
    extern __shared__ float sm[];
    float* qTs = sm;            // [d][128]
    float* kT  = sm + 64*128;   // 2 buffers of [d][64]

    const int bh = blockIdx.y;
    const int q0 = blockIdx.x << 7;
    const int tid = threadIdx.x;
    const int rg = tid >> 4;    // 16 x 8q
    const int cg = tid & 15;    // 16 x 4s

    for (int i = tid; i < 2048; i += 256) {
        int d = i >> 5, g = (i & 31) << 2;
        *(float4*)&qTs[d*128 + g] = *(const float4*)&g_qcT[(size_t)(bh*HDIM + d)*SEQ + q0 + g];
    }

    float bsc[8];
    int   bix[8];
#pragma unroll
    for (int i = 0; i < 8; i++) { bsc[i] = -FLTMAX; bix[i] = 0; }

    const float* qb = &qTs[rg << 3];
    ssa_issue(0, kT, tid, bh);

    for (int it = 0; it < 16; it++) {
        const int s0 = it << 6;
        cpa_wait0();
        __syncthreads();
        if (it + 1 < 16) ssa_issue(s0 + 64, kT + ((it + 1) & 1) * 4096, tid, bh);

        const float* kb = kT + (it & 1) * 4096 + (cg << 2);

        ull sc2[4][4];
#pragma unroll
        for (int i = 0; i < 4; i++)
#pragma unroll
            for (int j = 0; j < 4; j++) sc2[i][j] = 0ull;

#pragma unroll 4
        for (int d = 0; d < 64; d++) {
            ulonglong2 q01 = *(const ulonglong2*)(qb + d*128);
            ulonglong2 q23 = *(const ulonglong2*)(qb + d*128 + 4);
            float4 kv = *(const float4*)(kb + d*64);
            ull k0 = dup2(kv.x), k1 = dup2(kv.y), k2 = dup2(kv.z), k3 = dup2(kv.w);
            fma2(sc2[0][0], q01.x, k0); fma2(sc2[0][1], q01.x, k1);
            fma2(sc2[0][2], q01.x, k2); fma2(sc2[0][3], q01.x, k3);
            fma2(sc2[1][0], q01.y, k0); fma2(sc2[1][1], q01.y, k1);
            fma2(sc2[1][2], q01.y, k2); fma2(sc2[1][3], q01.y, k3);
            fma2(sc2[2][0], q23.x, k0); fma2(sc2[2][1], q23.x, k1);
            fma2(sc2[2][2], q23.x, k2); fma2(sc2[2][3], q23.x, k3);
            fma2(sc2[3][0], q23.y, k0); fma2(sc2[3][1], q23.y, k1);
            fma2(sc2[3][2], q23.y, k2); fma2(sc2[3][3], q23.y, k3);
        }

#pragma unroll
        for (int qp = 0; qp < 4; qp++) {
            float s0v[4], s1v[4];
#pragma unroll
            for (int j = 0; j < 4; j++) unpack2(sc2[qp][j], s0v[j], s1v[j]);
            int i0 = (qp << 1), i1 = i0 + 1;
            float4 mk0 = *(const float4*)&sem_map[(size_t)(q0 + (rg<<3) + i0)*SEQ + s0 + (cg<<2)];
            float4 mk1 = *(const float4*)&sem_map[(size_t)(q0 + (rg<<3) + i1)*SEQ + s0 + (cg<<2)];
            float ma[4] = {mk0.x, mk0.y, mk0.z, mk0.w};
            float mb[4] = {mk1.x, mk1.y, mk1.z, mk1.w};
#pragma unroll
            for (int j = 0; j < 4; j++) {
                float va = (ma[j] < 0.5f) ? -FLTMAX : s0v[j];
                float vb = (mb[j] < 0.5f) ? -FLTMAX : s1v[j];
                if (va > bsc[i0]) { bsc[i0] = va; bix[i0] = s0 + (cg<<2) + j; }
                if (vb > bsc[i1]) { bsc[i1] = vb; bix[i1] = s0 + (cg<<2) + j; }
            }
        }
    }

#pragma unroll
    for (int i = 0; i < 8; i++) {
        float bs = bsc[i]; int bi = bix[i];
#pragma unroll
        for (int off = 1; off < 16; off <<= 1) {
            float os = __shfl_xor_sync(0xffffffffu, bs, off, 16);
            int   oi = __shfl_xor_sync(0xffffffffu, bi, off, 16);
            if (os > bs || (os == bs && oi < bi)) { bs = os; bi = oi; }
        }
        if (cg == 0) g_idx[bh*SEQ + q0 + (rg<<3) + i] = bi;
    }
}

// ---------------- SCA kernel (R13 + paired STS.128 weight stores) ---------------
#define SCA_QT   0
#define SCA_KT   4096
#define SCA_VT   8192
#define SCA_WT   12544
#define SCA_L    16896
#define SCA_SM_FLOATS 16960

__device__ __forceinline__ void sca_issue_k(int s0, float* kT, int tid, int bh) {
    for (int i = tid; i < 1024; i += 128) {
        int d = i >> 4, g = (i & 15) << 2;
        cpa16(sptr(kT + d*64 + g), &g_ksT[(size_t)(bh*HDIM + d)*SEQ + s0 + g]);
    }
    cpa_commit();
}
__device__ __forceinline__ void sca_issue_v(int s0, float* vT, int tid, int b, int h) {
    for (int i = tid; i < 1024; i += 128) {
        int d = i >> 4, g = (i & 15) << 2;
        cpa16(sptr(vT + d*68 + g), &g_v[(size_t)((s0 + d)*BSZ + b)*EMB + h*HDIM + g]);
    }
    cpa_commit();
}

__global__ __launch_bounds__(128)
void sca_kernel(const float* __restrict__ sem_map, float* __restrict__ Ocomb) {
    extern __shared__ float sm[];
    float* qTs  = sm + SCA_QT;
    float* kT   = sm + SCA_KT;
    float* vT   = sm + SCA_VT;
    float* wts  = sm + SCA_WT;
    float* sl   = sm + SCA_L;

    const int bh = blockIdx.y, b = bh >> 3, h = bh & 7;
    const int q0 = blockIdx.x << 6;
    const int tid = threadIdx.x;
    const int rg = tid >> 4;     // 8 groups x 8q
    const int cg = tid & 15;     // 16 groups x 4s

    for (int i = tid; i < 1024; i += 128) {
        int d = i >> 4, g = (i & 15) << 2;
        *(float4*)&qTs[d*64 + g] = *(const float4*)&g_qsT[(size_t)(bh*HDIM + d)*SEQ + q0 + g];
    }

    float lrun[8];
#pragma unroll
    for (int i = 0; i < 8; i++) lrun[i] = 0.f;

    ull acc2[4][4];
#pragma unroll
    for (int i = 0; i < 4; i++)
#pragma unroll
        for (int j = 0; j < 4; j++) acc2[i][j] = 0ull;

    const float* qb = &qTs[rg << 3];
    const float* kb = &kT[cg << 2];
    const float* wb = &wts[rg << 3];
    const float* vb = &vT[cg << 2];

    sca_issue_k(0, kT, tid, bh);          // group: k(0)

    for (int it = 0; it < 16; it++) {
        const int s0 = it << 6;
        __syncthreads();                   // prev PV done reading vT/wt
        sca_issue_v(s0, vT, tid, b, h);    // group: v(it) — loads during score
        cpa_wait1();                       // k(it) retired; v(it) in flight
        __syncthreads();

        ull sc2[4][4];
#pragma unroll
        for (int i = 0; i < 4; i++)
#pragma unroll
            for (int j = 0; j < 4; j++) sc2[i][j] = 0ull;

#pragma unroll 4
        for (int d = 0; d < 64; d++) {
            ulonglong2 q01 = *(const ulonglong2*)(qb + d*64);
            ulonglong2 q23 = *(const ulonglong2*)(qb + d*64 + 4);
            float4 kv = *(const float4*)(kb + d*64);
            ull k0 = dup2(kv.x), k1 = dup2(kv.y), k2 = dup2(kv.z), k3 = dup2(kv.w);
            fma2(sc2[0][0], q01.x, k0); fma2(sc2[0][1], q01.x, k1);
            fma2(sc2[0][2], q01.x, k2); fma2(sc2[0][3], q01.x, k3);
            fma2(sc2[1][0], q01.y, k0); fma2(sc2[1][1], q01.y, k1);
            fma2(sc2[1][2], q01.y, k2); fma2(sc2[1][3], q01.y, k3);
            fma2(sc2[2][0], q23.x, k0); fma2(sc2[2][1], q23.x, k1);
            fma2(sc2[2][2], q23.x, k2); fma2(sc2[2][3], q23.x, k3);
            fma2(sc2[3][0], q23.y, k0); fma2(sc2[3][1], q23.y, k1);
            fma2(sc2[3][2], q23.y, k2); fma2(sc2[3][3], q23.y, k3);
        }

        // ---- mask + exp (no max subtraction); buffer pairs, then STS.128 ----
        ull wrow[4][4];   // [j][qp] q-pairs
#pragma unroll
        for (int qp = 0; qp < 4; qp++) {
            float sA[4], sB[4];
#pragma unroll
            for (int j = 0; j < 4; j++) unpack2(sc2[qp][j], sA[j], sB[j]);
            int iA = qp << 1, iB = iA + 1;
            float4 mkA = *(const float4*)&sem_map[(size_t)(q0 + (rg<<3) + iA)*SEQ + s0 + (cg<<2)];
            float4 mkB = *(const float4*)&sem_map[(size_t)(q0 + (rg<<3) + iB)*SEQ + s0 + (cg<<2)];
            float wA[4], wB[4];
            wA[0] = (mkA.x < 0.5f) ? 0.f : __expf(sA[0]);
            wA[1] = (mkA.y < 0.5f) ? 0.f : __expf(sA[1]);
            wA[2] = (mkA.z < 0.5f) ? 0.f : __expf(sA[2]);
            wA[3] = (mkA.w < 0.5f) ? 0.f : __expf(sA[3]);
            wB[0] = (mkB.x < 0.5f) ? 0.f : __expf(sB[0]);
            wB[1] = (mkB.y < 0.5f) ? 0.f : __expf(sB[1]);
            wB[2] = (mkB.z < 0.5f) ? 0.f : __expf(sB[2]);
            wB[3] = (mkB.w < 0.5f) ? 0.f : __expf(sB[3]);
            lrun[iA] += (wA[0] + wA[1]) + (wA[2] + wA[3]);
            lrun[iB] += (wB[0] + wB[1]) + (wB[2] + wB[3]);
#pragma unroll
            for (int j = 0; j < 4; j++) wrow[j][qp] = pack2(wA[j], wB[j]);
        }
#pragma unroll
        for (int j = 0; j < 4; j++) {
            ulonglong2 v0, v1;
            v0.x = wrow[j][0]; v0.y = wrow[j][1];
            v1.x = wrow[j][2]; v1.y = wrow[j][3];
            float* base = &wts[((cg<<2)+j)*68 + (rg<<3)];
            *(ulonglong2*)(base)     = v0;
            *(ulonglong2*)(base + 4) = v1;
        }
        __syncthreads();                   // kT free; wt written

        if (it + 1 < 16) {
            sca_issue_k(s0 + 64, kT, tid, bh);  // k(it+1) — loads during PV
            cpa_wait1();                   // v(it) retired; k(it+1) in flight
        } else {
            cpa_wait0();                   // v(15) retired
        }
        __syncthreads();

#pragma unroll 4
        for (int s = 0; s < 64; s++) {
            ulonglong2 w01 = *(const ulonglong2*)(wb + s*68);
            ulonglong2 w23 = *(const ulonglong2*)(wb + s*68 + 4);
            float4 vv = *(const float4*)(vb + s*68);
            ull v0 = dup2(vv.x), v1 = dup2(vv.y), v2 = dup2(vv.z), v3 = dup2(vv.w);
            fma2(acc2[0][0], w01.x, v0); fma2(acc2[0][1], w01.x, v1);
            fma2(acc2[0][2], w01.x, v2); fma2(acc2[0][3], w01.x, v3);
            fma2(acc2[1][0], w01.y, v0); fma2(acc2[1][1], w01.y, v1);
            fma2(acc2[1][2], w01.y, v2); fma2(acc2[1][3], w01.y, v3);
            fma2(acc2[2][0], w23.x, v0); fma2(acc2[2][1], w23.x, v1);
            fma2(acc2[2][2], w23.x, v2); fma2(acc2[2][3], w23.x, v3);
            fma2(acc2[3][0], w23.y, v0); fma2(acc2[3][1], w23.y, v1);
            fma2(acc2[3][2], w23.y, v2); fma2(acc2[3][3], w23.y, v3);
        }
    }

#pragma unroll
    for (int i = 0; i < 8; i++) {
        float s = lrun[i];
#pragma unroll
        for (int off = 1; off < 16; off <<= 1)
            s += __shfl_xor_sync(0xffffffffu, s, off, 16);
        if (cg == 0) sl[(rg<<3) + i] = s;
    }
    __syncthreads();

#pragma unroll
    for (int qp = 0; qp < 4; qp++) {
        float aA[4], aB[4];
#pragma unroll
        for (int j = 0; j < 4; j++) unpack2(acc2[qp][j], aA[j], aB[j]);
        int rA = (rg<<3) + (qp<<1), rB = rA + 1;
        float rlA = 1.0f / sl[rA];
        float rlB = 1.0f / sl[rB];
        int biA = g_idx[bh*SEQ + q0 + rA];
        int biB = g_idx[bh*SEQ + q0 + rB];
        float4 vA = *(const float4*)&g_v[(size_t)(biA*BSZ + b)*EMB + h*HDIM + (cg<<2)];
        float4 vB = *(const float4*)&g_v[(size_t)(biB*BSZ + b)*EMB + h*HDIM + (cg<<2)];
        float4 oA, oB;
        oA.x = T1C*aA[0]*rlA + T2C*vA.x;  oA.y = T1C*aA[1]*rlA + T2C*vA.y;
        oA.z = T1C*aA[2]*rlA + T2C*vA.z;  oA.w = T1C*aA[3]*rlA + T2C*vA.w;
        oB.x = T1C*aB[0]*rlB + T2C*vB.x;  oB.y = T1C*aB[1]*rlB + T2C*vB.y;
        oB.z = T1C*aB[2]*rlB + T2C*vB.z;  oB.w = T1C*aB[3]*rlB + T2C*vB.w;
        *(float4*)&Ocomb[(size_t)((q0 + rA)*BSZ + b)*EMB + h*HDIM + (cg<<2)] = oA;
        *(float4*)&Ocomb[(size_t)((q0 + rB)*BSZ + b)*EMB + h*HDIM + (cg<<2)] = oB;
    }
}

// -------------------------------------------------------------------------------
extern "C" void kernel_launch(void* const* d_in, const int* in_sizes, int n_in,
                              void* d_out, int out_size) {
    const float* query = (const float*)d_in[0];
    const float* key   = (const float*)d_in[1];
    const float* value = (const float*)d_in[2];
    const float* qsem  = (const float*)d_in[3];
    const float* ksem  = (const float*)d_in[4];
    const float* smap  = (const float*)d_in[5];
    const float* Wi    = (const float*)d_in[6];
    const float* bi    = (const float*)d_in[7];
    const float* Wo    = (const float*)d_in[8];
    const float* bo    = (const float*)d_in[9];
    float* out = (float*)d_out;

    float *p_qs, *p_ks, *p_qc, *p_kc, *p_v, *p_qsT, *p_ksT, *p_qcT, *p_kcT, *p_o;
    cudaGetSymbolAddress((void**)&p_qs,  g_qs);
    cudaGetSymbolAddress((void**)&p_ks,  g_ks);
    cudaGetSymbolAddress((void**)&p_qc,  g_qc);
    cudaGetSymbolAddress((void**)&p_kc,  g_kc);
    cudaGetSymbolAddress((void**)&p_v,   g_v);
    cudaGetSymbolAddress((void**)&p_qsT, g_qsT);
    cudaGetSymbolAddress((void**)&p_ksT, g_ksT);
    cudaGetSymbolAddress((void**)&p_qcT, g_qcT);
    cudaGetSymbolAddress((void**)&p_kcT, g_kcT);
    cudaGetSymbolAddress((void**)&p_o,   g_o);

    static int init_done = 0;
    if (!init_done) {
        cudaFuncSetAttribute(sca_kernel, cudaFuncAttributeMaxDynamicSharedMemorySize, SCA_SM_FLOATS*4);
        cudaFuncSetAttribute(ssa_kernel, cudaFuncAttributeMaxDynamicSharedMemorySize, SSA_SM_FLOATS*4);
        init_done = 1;
    }

    GemmBatch gb;
    gb.x[0] = qsem;  gb.c[0] = p_qs; gb.woff[0] = 0;
    gb.x[1] = ksem;  gb.c[1] = p_ks; gb.woff[1] = 512;
    gb.x[2] = query; gb.c[2] = p_qc; gb.woff[2] = 0;
    gb.x[3] = key;   gb.c[3] = p_kc; gb.woff[3] = 512;
    gb.x[4] = value; gb.c[4] = p_v;  gb.woff[4] = 1024;
    gemm_bias5<<<dim3(EMB/128, NROWS/128, 5), 256>>>(gb, Wi, bi);

    TransBatch tb;
    tb.src[0] = p_qs; tb.dst[0] = p_qsT; tb.scale[0] = 0.125f;
    tb.src[1] = p_ks; tb.dst[1] = p_ksT; tb.scale[1] = 1.0f;
    tb.src[2] = p_qc; tb.dst[2] = p_qcT; tb.scale[2] = 0.125f;
    tb.src[3] = p_kc; tb.dst[3] = p_kcT; tb.scale[3] = 1.0f;
    transpose_head4<<<dim3(SEQ/32, HDIM/32, 4*NBH), 256>>>(tb);

    ssa_kernel<<<dim3(SEQ/128, NBH), 256, SSA_SM_FLOATS*4>>>(smap);
    sca_kernel<<<dim3(SEQ/64, NBH), 128, SCA_SM_FLOATS*4>>>(smap, p_o);

    gemm_bias<<<dim3(EMB/128, NROWS/128), 256>>>(p_o, Wo, bo, out, T1C + T2C);
}